// round 2
// baseline (speedup 1.0000x reference)
#include <cuda_runtime.h>
#include <cstdint>

typedef unsigned long long ull;

#define B_  32
#define S_  128
#define H_  512
#define D_  512
#define V_  32000
#define F_  768
#define G4  2048   // 4*H

// ---------------- scratch (device globals; no allocation allowed) ----------------
__device__ float g_yim[B_ * D_];                 // image dense output
__device__ float g_Xg[(S_ + 1) * B_ * D_];       // gathered step inputs (warmup + embeds)
__device__ float g_xU[(S_ + 1) * B_ * G4];       // precomputed x @ Uh0 for every step
__device__ float g_Wcat[1024 * G4];              // [Wh1 ; M01=Wxh0@Uh1]
__device__ float g_b1eff[G4];                    // bw1+bu1+bxh0@Uh1
__device__ float g_hcat[B_ * 1024];              // per row: [h1 (0..511) | h0 (512..1023)]
__device__ float g_c0s[B_ * H_];
__device__ float g_c1s[B_ * H_];
__device__ float g_part[16 * B_ * G4];           // split-K partial sums
__device__ float g_H1s[S_ * B_ * H_];            // h1 per step (t-major)
__device__ float g_ys[S_ * B_ * D_];             // xh_dense outputs

// ---------------- packed fp32x2 helpers (sm_100+ FFMA2) ----------------
__device__ __forceinline__ ull pack2(float x, float y) {
    ull r;
    asm("mov.b64 %0, {%1, %2};" : "=l"(r) : "f"(x), "f"(y));
    return r;
}
__device__ __forceinline__ void ffma2(ull& d, ull a, ull b) {
    asm("fma.rn.f32x2 %0, %1, %2, %0;" : "+l"(d) : "l"(a), "l"(b));
}
__device__ __forceinline__ float2 unpack2(ull v) {
    float2 r;
    asm("mov.b64 {%0, %1}, %2;" : "=f"(r.x), "=f"(r.y) : "l"(v));
    return r;
}

// ---------------- init: scatter h0/c0 into state buffers ----------------
__global__ void init_state_kernel(const float* __restrict__ h0,
                                  const float* __restrict__ c0,
                                  float* __restrict__ hcat,
                                  float* __restrict__ c0s,
                                  float* __restrict__ c1s) {
    int idx = blockIdx.x * 256 + threadIdx.x;   // 2*32*512 = 32768
    int l = idx >> 14;
    int b = (idx >> 9) & 31;
    int j = idx & 511;
    float h = h0[idx], c = c0[idx];
    if (l == 0) { hcat[b * 1024 + 512 + j] = h; c0s[b * 512 + j] = c; }
    else        { hcat[b * 1024 + j] = h;       c1s[b * 512 + j] = c; }
}

// ---------------- gather step inputs: slot0 = y_im, slot t = embed[tokens[:,t-1]] ----------------
__global__ void gather_kernel(const float* __restrict__ yim,
                              const float* __restrict__ embed,
                              const int* __restrict__ tokens,
                              float* __restrict__ Xg) {
    int v = blockIdx.x * 256 + threadIdx.x;     // float4 index; total (S+1)*B*D/4 = 528384
    int d4 = v & 127;
    int bt = v >> 7;
    int b = bt & 31;
    int t = bt >> 5;
    const float4* src;
    if (t == 0) src = (const float4*)(yim + b * 512);
    else        src = (const float4*)(embed + (size_t)tokens[b * 128 + (t - 1)] * 512);
    ((float4*)Xg)[v] = src[d4];
}

// ---------------- b1eff = bw1 + bu1 + bxh0 @ Uh1 ----------------
__global__ void b1eff_kernel(const float* __restrict__ bw, const float* __restrict__ bu,
                             const float* __restrict__ bxh, const float* __restrict__ Uh,
                             float* __restrict__ b1) {
    int n = blockIdx.x * 256 + threadIdx.x;     // 2048
    float acc = bw[2048 + n] + bu[2048 + n];
    const float* U1 = Uh + 512 * 2048;
    for (int k = 0; k < 512; k++) acc += bxh[k] * U1[k * 2048 + n];
    b1[n] = acc;
}

// ---------------- cell GEMM: partial[ks][b][n] = sum_{k in slice} A[b][k]*W[k][n] ----------------
// A: [32][lda] row-major, W: [K][2048] row-major. Grid (16 n-blocks, K/64 k-slices), 128 threads.
__global__ __launch_bounds__(128) void cell_gemm_kernel(const float* __restrict__ A, int lda,
                                                        const float* __restrict__ W,
                                                        float* __restrict__ part) {
    __shared__ __align__(16) float hs[64][36];  // padded: rows 144B (16B-aligned, low conflicts)
    int tid = threadIdx.x;
    int kbase = blockIdx.y * 64;
    #pragma unroll
    for (int i = tid; i < 2048; i += 128) {
        int b = i >> 6;
        int kk = i & 63;
        hs[kk][b] = A[b * lda + kbase + kk];
    }
    __syncthreads();
    int ncol = blockIdx.x * 128 + tid;
    const float* Wp = W + (size_t)kbase * 2048 + ncol;
    ull acc[16];
    #pragma unroll
    for (int q = 0; q < 16; q++) acc[q] = 0ULL;

    for (int k0 = 0; k0 < 64; k0 += 8) {
        float wv[8];
        #pragma unroll
        for (int j = 0; j < 8; j++) wv[j] = Wp[(size_t)(k0 + j) * 2048];  // batched -> MLP 8
        #pragma unroll
        for (int j = 0; j < 8; j++) {
            ull w2 = pack2(wv[j], wv[j]);
            const float* hr = &hs[k0 + j][0];
            #pragma unroll
            for (int p = 0; p < 8; p++) {
                ulonglong2 hh = *(const ulonglong2*)(hr + p * 4);  // h[4p..4p+3] as 2 pairs
                ffma2(acc[2 * p], w2, hh.x);
                ffma2(acc[2 * p + 1], w2, hh.y);
            }
        }
    }
    float* pp = part + (size_t)(blockIdx.y * 32) * 2048 + ncol;
    #pragma unroll
    for (int q = 0; q < 16; q++) {
        float2 v = unpack2(acc[q]);
        pp[(2 * q) * 2048] = v.x;
        pp[(2 * q + 1) * 2048] = v.y;
    }
}

// ---------------- combine partials + activations + state update ----------------
__global__ void cell_combine_kernel(const float* __restrict__ part, int nsl,
                                    const float* __restrict__ xU,
                                    const float* __restrict__ bA, const float* __restrict__ bB,
                                    float* __restrict__ cstate,
                                    float* __restrict__ hout, int hstride,
                                    float* __restrict__ h1s) {
    int idx = blockIdx.x * 256 + threadIdx.x;   // 32*512
    int b = idx >> 9;
    int j = idx & 511;
    float gf = 0.f, gi = 0.f, go = 0.f, gc = 0.f;
    const float* p = part + b * 2048 + j;
    for (int s = 0; s < nsl; s++) {
        gf += p[0]; gi += p[512]; go += p[1024]; gc += p[1536];
        p += 32 * 2048;
    }
    if (xU) {
        const float* x = xU + b * 2048 + j;
        gf += x[0]; gi += x[512]; go += x[1024]; gc += x[1536];
    }
    gf += bA[j]; gi += bA[512 + j]; go += bA[1024 + j]; gc += bA[1536 + j];
    if (bB) { gf += bB[j]; gi += bB[512 + j]; go += bB[1024 + j]; gc += bB[1536 + j]; }

    float f  = 1.f / (1.f + __expf(-gf));
    float ii = 1.f / (1.f + __expf(-gi));
    float o  = 1.f / (1.f + __expf(-go));
    float cn = f * cstate[idx] + ii * tanhf(gc);
    float hn = o * tanhf(cn);
    cstate[idx] = cn;
    hout[b * hstride + j] = hn;
    if (h1s) h1s[idx] = hn;
}

// ---------------- general SGEMM: C = A[M,K] @ B[K,N] (+bias), optional (t,b)->(b,t) row permute ----------------
// 128x128 tile, BK=16, 8x8 per thread, packed f32x2 FFMA. Requires N%128==0, K%16==0. M guarded.
__global__ __launch_bounds__(256, 2) void sgemm_kernel(const float* __restrict__ A,
                                                       const float* __restrict__ Bm,
                                                       const float* __restrict__ bias,
                                                       float* __restrict__ C,
                                                       int M, int N, int K, int permute) {
    __shared__ __align__(16) float As[16][132];
    __shared__ __align__(16) float Bs[16][128];
    int tid = threadIdx.x;
    int m0 = blockIdx.y * 128;
    int n0 = blockIdx.x * 128;
    int a_m = tid >> 2;
    int a_k = (tid & 3) << 2;
    int b_k = tid >> 5;
    int b_n = (tid & 31) << 2;
    int tm0 = (tid >> 4) << 3;
    int tn0 = (tid & 15) << 3;
    ull acc[8][4];
    #pragma unroll
    for (int i = 0; i < 8; i++)
        #pragma unroll
        for (int j = 0; j < 4; j++) acc[i][j] = 0ULL;

    for (int k0 = 0; k0 < K; k0 += 16) {
        #pragma unroll
        for (int h = 0; h < 2; h++) {
            int gm = m0 + a_m + h * 64;
            float4 av = make_float4(0.f, 0.f, 0.f, 0.f);
            if (gm < M) av = *(const float4*)(A + (size_t)gm * K + k0 + a_k);
            As[a_k + 0][a_m + h * 64] = av.x;
            As[a_k + 1][a_m + h * 64] = av.y;
            As[a_k + 2][a_m + h * 64] = av.z;
            As[a_k + 3][a_m + h * 64] = av.w;
        }
        #pragma unroll
        for (int h = 0; h < 2; h++) {
            int gk = k0 + b_k + h * 8;
            *(float4*)&Bs[b_k + h * 8][b_n] = *(const float4*)(Bm + (size_t)gk * N + n0 + b_n);
        }
        __syncthreads();
        #pragma unroll
        for (int kk = 0; kk < 16; kk++) {
            float4 a0 = *(const float4*)&As[kk][tm0];
            float4 a1 = *(const float4*)&As[kk][tm0 + 4];
            ull b2[4];
            #pragma unroll
            for (int j = 0; j < 4; j++) b2[j] = *(const ull*)&Bs[kk][tn0 + 2 * j];
            float av[8] = {a0.x, a0.y, a0.z, a0.w, a1.x, a1.y, a1.z, a1.w};
            #pragma unroll
            for (int i = 0; i < 8; i++) {
                ull a2 = pack2(av[i], av[i]);
                #pragma unroll
                for (int j = 0; j < 4; j++) ffma2(acc[i][j], a2, b2[j]);
            }
        }
        __syncthreads();
    }
    #pragma unroll
    for (int i = 0; i < 8; i++) {
        int r = m0 + tm0 + i;
        if (r < M) {
            int ro = permute ? ((r & 31) * 128 + (r >> 5)) : r;  // (t*32+b) -> b*S+t
            float o_[8];
            #pragma unroll
            for (int j = 0; j < 4; j++) {
                float2 v = unpack2(acc[i][j]);
                o_[2 * j] = v.x;
                o_[2 * j + 1] = v.y;
            }
            if (bias) {
                #pragma unroll
                for (int j = 0; j < 8; j++) o_[j] += bias[n0 + tn0 + j];
            }
            float* cp = C + (size_t)ro * N + n0 + tn0;
            *(float4*)cp = make_float4(o_[0], o_[1], o_[2], o_[3]);
            *(float4*)(cp + 4) = make_float4(o_[4], o_[5], o_[6], o_[7]);
        }
    }
}

// ---------------- host orchestration ----------------
extern "C" void kernel_launch(void* const* d_in, const int* in_sizes, int n_in,
                              void* d_out, int out_size) {
    const float* im_feat = (const float*)d_in[0];
    const int*   tokens  = (const int*)d_in[1];
    const float* h0      = (const float*)d_in[2];
    const float* c0      = (const float*)d_in[3];
    const float* embed   = (const float*)d_in[4];
    const float* W_im    = (const float*)d_in[5];
    const float* b_im    = (const float*)d_in[6];
    const float* Wh      = (const float*)d_in[7];
    const float* bw      = (const float*)d_in[8];
    const float* Uh      = (const float*)d_in[9];
    const float* bu      = (const float*)d_in[10];
    const float* Wxh     = (const float*)d_in[11];
    const float* bxh     = (const float*)d_in[12];
    const float* Wc      = (const float*)d_in[13];
    const float* bc      = (const float*)d_in[14];
    float* out = (float*)d_out;

    float *yim, *Xg, *xU, *Wcat, *b1eff, *hcat, *c0s, *c1s, *part, *H1s, *ys;
    cudaGetSymbolAddress((void**)&yim,   g_yim);
    cudaGetSymbolAddress((void**)&Xg,    g_Xg);
    cudaGetSymbolAddress((void**)&xU,    g_xU);
    cudaGetSymbolAddress((void**)&Wcat,  g_Wcat);
    cudaGetSymbolAddress((void**)&b1eff, g_b1eff);
    cudaGetSymbolAddress((void**)&hcat,  g_hcat);
    cudaGetSymbolAddress((void**)&c0s,   g_c0s);
    cudaGetSymbolAddress((void**)&c1s,   g_c1s);
    cudaGetSymbolAddress((void**)&part,  g_part);
    cudaGetSymbolAddress((void**)&H1s,   g_H1s);
    cudaGetSymbolAddress((void**)&ys,    g_ys);

    // states
    init_state_kernel<<<128, 256>>>(h0, c0, hcat, c0s, c1s);
    // y_im = im_feat @ W_im + b_im        [32,768]@[768,512]
    sgemm_kernel<<<dim3(D_ / 128, 1), 256>>>(im_feat, W_im, b_im, yim, B_, D_, F_, 0);
    // gather step inputs
    gather_kernel<<<((S_ + 1) * B_ * D_ / 4) / 256, 256>>>(yim, embed, tokens, Xg);
    // xU = Xg @ Uh0                        [4128,512]@[512,2048]
    sgemm_kernel<<<dim3(G4 / 128, ((S_ + 1) * B_ + 127) / 128), 256>>>(
        Xg, Uh, nullptr, xU, (S_ + 1) * B_, G4, D_, 0);
    // Wcat = [Wh1 ; Wxh0 @ Uh1]
    cudaMemcpyAsync(Wcat, Wh + (size_t)H_ * G4, sizeof(float) * H_ * G4,
                    cudaMemcpyDeviceToDevice, 0);
    sgemm_kernel<<<dim3(G4 / 128, H_ / 128), 256>>>(
        Wxh, Uh + (size_t)D_ * G4, nullptr, Wcat + (size_t)H_ * G4, H_, G4, H_, 0);
    // b1eff
    b1eff_kernel<<<G4 / 256, 256>>>(bw, bu, bxh, Uh, b1eff);

    // recurrence: t=0 is the image warm-up step, t=1..S are caption steps
    for (int t = 0; t <= S_; t++) {
        // layer 0: g0 = h0 @ Wh0 (split-K 8) + xU[t] + bw0 + bu0
        cell_gemm_kernel<<<dim3(16, 8), 128>>>(hcat + 512, 1024, Wh, part);
        cell_combine_kernel<<<64, 256>>>(part, 8, xU + (size_t)t * B_ * G4,
                                         bw, bu, c0s, hcat + 512, 1024, nullptr);
        // layer 1: g1 = [h1|h0'] @ [Wh1;M01] (split-K 16) + b1eff
        cell_gemm_kernel<<<dim3(16, 16), 128>>>(hcat, 1024, Wcat, part);
        cell_combine_kernel<<<64, 256>>>(part, 16, nullptr,
                                         b1eff, nullptr, c1s, hcat, 1024,
                                         (t > 0) ? (H1s + (size_t)(t - 1) * B_ * H_) : nullptr);
    }

    // ys = H1s @ Wxh1 + bxh1               [4096,512]@[512,512]
    sgemm_kernel<<<dim3(D_ / 128, S_ * B_ / 128), 256>>>(
        H1s, Wxh + (size_t)H_ * D_, bxh + D_, ys, S_ * B_, D_, H_, 0);
    // logits = ys @ Wc + bc                [4096,512]@[512,32000], rows permuted (t,b)->(b,t)
    sgemm_kernel<<<dim3(V_ / 128, S_ * B_ / 128), 256>>>(
        ys, Wc, bc, out, S_ * B_, V_, D_, 1);
}